// round 9
// baseline (speedup 1.0000x reference)
#include <cuda_runtime.h>
#include <cuda_bf16.h>

#define EPSF 1e-9f
#define WPB  16              // warps per block (512 threads)
#define TARGET_WARPS 7104    // 148 SMs * 3 blocks * 16 warps
#define MAX_STAGE 352        // max staged bodies per block (2*len)
#define RSPLIT 8             // reduce threads per body

// partial sums: unit index (c*groups + g) * 32 + lane
__device__ float2 g_part[16384 * 32];

__global__ __launch_bounds__(512, 3)
void pairs_kernel(const float2* __restrict__ cpos,
                  const float*  __restrict__ crad,
                  const float2* __restrict__ apos,
                  const float2* __restrict__ ahalf,
                  int nc, int na, int gc, int groups, int C, int len)
{
    __shared__ float4 s_body[MAX_STAGE];

    const int lane = threadIdx.x & 31;
    const int warp = threadIdx.x >> 5;
    const int unit = blockIdx.x * WPB + warp;
    const int L = nc + na;

    // ---- block-level staging: chunk range shared by (almost) all warps ----
    const int u0 = blockIdx.x * WPB;
    const int c0 = u0 / groups;
    const int lo_blk = c0 * len;
    const int hi_blk = min(L, lo_blk + 2 * len);

    for (int t = lo_blk + threadIdx.x; t < hi_blk; t += 512) {
        float4 v;
        if (t < nc) {
            float2 p = cpos[t];
            v = make_float4(p.x, p.y, 0.5f * crad[t], 0.0f);
        } else {
            float2 p = apos[t - nc];
            float2 h = ahalf[t - nc];
            v = make_float4(p.x, p.y, h.x, h.y);
        }
        s_body[t - lo_blk] = v;
    }
    __syncthreads();

    if (unit >= groups * C) return;

    const int c = unit / groups;
    const int g = unit - c * groups;
    const int lo = c * len;
    const int hi = min(L, lo + len);
    const float4* __restrict__ sb = s_body - lo_blk;   // index by flattened t

    float ax = 0.0f, ay = 0.0f;

    if (g < gc) {
        // ------------- circle body -------------
        int i  = g * 32 + lane;
        int ii = min(i, nc - 1);
        const float2 pp = cpos[ii];
        const float rih = 0.5f * crad[ii];
        const float px = pp.x, py = pp.y;

        // circle vs circle: t in [lo, min(hi,nc))
        int e1 = min(hi, nc);
        #pragma unroll 8
        for (int t = lo; t < e1; ++t) {
            float4 q = sb[t];
            float dx = px - q.x, dy = py - q.y;
            float d2 = fmaf(dx, dx, dy * dy);
            float rsh = rih + q.z;
            float inv = rsqrtf(d2);                       // inf/huge OK, select below
            float f = fmaxf(fmaf(rsh, inv, -0.5f), 0.0f);
            f = (d2 > EPSF) ? f : 0.0f;
            ax = fmaf(f, dx, ax);
            ay = fmaf(f, dy, ay);
        }

        // circle vs aabb: t in [max(lo,nc), hi)
        int s2 = max(lo, nc);
        #pragma unroll 4
        for (int t = s2; t < hi; ++t) {
            float4 q = sb[t];
            float rx = px - q.x, ry = py - q.y;
            float mx = fmaxf(fabsf(rx) - q.z, 0.0f);
            float my = fmaxf(fabsf(ry) - q.w, 0.0f);
            float d2 = fmaf(mx, mx, my * my);
            float inv = rsqrtf(d2);
            float f = fmaxf(fmaf(rih, inv, -0.5f), 0.0f);
            f = (d2 > EPSF) ? f : 0.0f;
            ax = fmaf(f, copysignf(mx, rx), ax);
            ay = fmaf(f, copysignf(my, ry), ay);
        }
    } else {
        // ------------- aabb body -------------
        int b  = (g - gc) * 32 + lane;
        int bb = min(b, na - 1);
        const float2 pp = apos[bb];
        const float2 hh = ahalf[bb];
        const float px = pp.x, py = pp.y;
        const float hx = hh.x, hy = hh.y;
        const int self_t = nc + bb;

        // circle pushes on box (equal-and-opposite): t in [lo, min(hi,nc))
        int e1 = min(hi, nc);
        #pragma unroll 4
        for (int t = lo; t < e1; ++t) {
            float4 q = sb[t];
            float rx = q.x - px, ry = q.y - py;
            float mx = fmaxf(fabsf(rx) - hx, 0.0f);
            float my = fmaxf(fabsf(ry) - hy, 0.0f);
            float d2 = fmaf(mx, mx, my * my);
            float inv = rsqrtf(d2);
            float f = fmaxf(fmaf(q.z, inv, -0.5f), 0.0f);
            f = (d2 > EPSF) ? f : 0.0f;
            ax = fmaf(-f, copysignf(mx, rx), ax);
            ay = fmaf(-f, copysignf(my, ry), ay);
        }

        // aabb vs aabb: t in [max(lo,nc), hi)
        int s2 = max(lo, nc);
        #pragma unroll 4
        for (int t = s2; t < hi; ++t) {
            float4 q = sb[t];
            float dax = px - q.x, day = py - q.y;
            float ovx = (hx + q.z) - fabsf(dax);
            float ovy = (hy + q.w) - fabsf(day);
            bool hit  = (t != self_t) & (ovx > 0.0f) & (ovy > 0.0f);
            bool usex = (ovx <= ovy);
            float pxs = copysignf(0.5f * ovx, dax);
            float pys = copysignf(0.5f * ovy, day);
            ax += (hit & usex)  ? pxs : 0.0f;
            ay += (hit & !usex) ? pys : 0.0f;
        }
    }

    g_part[unit * 32 + lane] = make_float2(ax, ay);
}

// 8 threads per body; shfl-tree combine over aligned 8-lane segments.
__global__ __launch_bounds__(512)
void reduce8_kernel(const float2* __restrict__ cpos,
                    const float2* __restrict__ apos,
                    float2* __restrict__ out,
                    int nc, int na, int gc, int groups, int C)
{
    int gid = blockIdx.x * blockDim.x + threadIdx.x;
    int b = gid >> 3;           // body
    int s = gid & 7;            // slice of partials
    int tot = nc + na;
    bool valid = (b < tot);
    int bcl = valid ? b : 0;

    int g, lane;
    if (bcl < nc) {
        g = bcl >> 5; lane = bcl & 31;
    } else {
        int a = bcl - nc;
        g = gc + (a >> 5); lane = a & 31;
    }

    float sx = 0.0f, sy = 0.0f;
    const int stride = groups * 32;
    const float2* p = &g_part[g * 32 + lane];
    if (valid) {
        #pragma unroll 5
        for (int c = s; c < C; c += RSPLIT) {
            float2 v = p[c * stride];
            sx += v.x;
            sy += v.y;
        }
    }

    // sum across the 8-lane aligned segment
    #pragma unroll
    for (int off = 1; off < RSPLIT; off <<= 1) {
        sx += __shfl_xor_sync(0xffffffffu, sx, off);
        sy += __shfl_xor_sync(0xffffffffu, sy, off);
    }

    if (valid && s == 0) {
        float2 base = (b < nc) ? cpos[b] : apos[b - nc];
        out[b] = make_float2(base.x + sx, base.y + sy);
    }
}

extern "C" void kernel_launch(void* const* d_in, const int* in_sizes, int n_in,
                              void* d_out, int out_size)
{
    const float2* cpos  = (const float2*)d_in[0];
    const float*  crad  = (const float*)d_in[1];
    const float2* apos  = (const float2*)d_in[2];
    const float2* ahalf = (const float2*)d_in[3];
    float2* out = (float2*)d_out;

    int nc = in_sizes[1];        // circle_radius element count
    int na = in_sizes[2] / 2;    // aabb_pos has na*2 elements

    int gc = (nc + 31) / 32;
    int ga = (na + 31) / 32;
    int groups = gc + ga;
    int L = nc + na;

    int C = TARGET_WARPS / groups;            // 192 groups -> 37
    if (C < 1) C = 1;
    // chunk length must fit the shared staging buffer (2*len <= MAX_STAGE)
    int minC = (L + (MAX_STAGE / 2 - 1)) / (MAX_STAGE / 2);
    if (C < minC) C = minC;
    if (groups * C > 16384) C = 16384 / groups;

    int len = (L + C - 1) / C;

    int units = groups * C;
    int grid1 = (units + WPB - 1) / WPB;

    pairs_kernel<<<grid1, 512>>>(cpos, crad, apos, ahalf,
                                 nc, na, gc, groups, C, len);

    int tot = nc + na;
    int grid2 = (tot * RSPLIT + 511) / 512;
    reduce8_kernel<<<grid2, 512>>>(cpos, apos, out, nc, na, gc, groups, C);
}

// round 10
// speedup vs baseline: 1.0063x; 1.0063x over previous
#include <cuda_runtime.h>
#include <cuda_bf16.h>

#define EPSF 1e-9f
#define WPB  16              // warps per block (512 threads)
#define TARGET_WARPS 7104    // 148 SMs * 3 blocks * 16 warps (subset of GB300's 152)
#define MAX_STAGE 352        // max staged bodies per block (2*len)

// partial sums, body-major: g_part[F*C + c], F = g*32+lane
__device__ float2 g_part[16384 * 32];
__device__ unsigned g_cnt = 0;
__device__ volatile unsigned g_rel = 0;

__global__ __launch_bounds__(512, 3)
void fused_kernel(const float2* __restrict__ cpos,
                  const float*  __restrict__ crad,
                  const float2* __restrict__ apos,
                  const float2* __restrict__ ahalf,
                  float2* __restrict__ out,
                  int nc, int na, int gc, int groups, int C, int len)
{
    __shared__ float4 s_body[MAX_STAGE];

    const int lane = threadIdx.x & 31;
    const int warp = threadIdx.x >> 5;
    const int unit = blockIdx.x * WPB + warp;
    const int L = nc + na;

    // ---- block-level staging: chunk range shared by all warps of this block ----
    const int u0 = blockIdx.x * WPB;
    const int c0 = u0 / groups;
    const int lo_blk = c0 * len;
    const int hi_blk = min(L, lo_blk + 2 * len);

    for (int t = lo_blk + threadIdx.x; t < hi_blk; t += 512) {
        float4 v;
        if (t < nc) {
            float2 p = cpos[t];
            v = make_float4(p.x, p.y, 0.5f * crad[t], 0.0f);
        } else {
            float2 p = apos[t - nc];
            float2 h = ahalf[t - nc];
            v = make_float4(p.x, p.y, h.x, h.y);
        }
        s_body[t - lo_blk] = v;
    }
    __syncthreads();

    // ================= phase 1: pair partial sums =================
    if (unit < groups * C) {
        const int c = unit / groups;
        const int g = unit - c * groups;
        const int lo = c * len;
        const int hi = min(L, lo + len);
        const float4* __restrict__ sb = s_body - lo_blk;   // index by flattened t

        float ax = 0.0f, ay = 0.0f;

        if (g < gc) {
            // ------------- circle body -------------
            int i  = g * 32 + lane;
            int ii = min(i, nc - 1);
            const float2 pp = cpos[ii];
            const float rih = 0.5f * crad[ii];
            const float px = pp.x, py = pp.y;

            int e1 = min(hi, nc);
            #pragma unroll 8
            for (int t = lo; t < e1; ++t) {
                float4 q = sb[t];
                float dx = px - q.x, dy = py - q.y;
                float d2 = fmaf(dx, dx, dy * dy);
                float rsh = rih + q.z;
                float inv = rsqrtf(d2);
                float f = fmaxf(fmaf(rsh, inv, -0.5f), 0.0f);
                f = (d2 > EPSF) ? f : 0.0f;
                ax = fmaf(f, dx, ax);
                ay = fmaf(f, dy, ay);
            }

            int s2 = max(lo, nc);
            #pragma unroll 4
            for (int t = s2; t < hi; ++t) {
                float4 q = sb[t];
                float rx = px - q.x, ry = py - q.y;
                float mx = fmaxf(fabsf(rx) - q.z, 0.0f);
                float my = fmaxf(fabsf(ry) - q.w, 0.0f);
                float d2 = fmaf(mx, mx, my * my);
                float inv = rsqrtf(d2);
                float f = fmaxf(fmaf(rih, inv, -0.5f), 0.0f);
                f = (d2 > EPSF) ? f : 0.0f;
                ax = fmaf(f, copysignf(mx, rx), ax);
                ay = fmaf(f, copysignf(my, ry), ay);
            }
        } else {
            // ------------- aabb body -------------
            int b  = (g - gc) * 32 + lane;
            int bb = min(b, na - 1);
            const float2 pp = apos[bb];
            const float2 hh = ahalf[bb];
            const float px = pp.x, py = pp.y;
            const float hx = hh.x, hy = hh.y;
            const int self_t = nc + bb;

            int e1 = min(hi, nc);
            #pragma unroll 4
            for (int t = lo; t < e1; ++t) {
                float4 q = sb[t];
                float rx = q.x - px, ry = q.y - py;
                float mx = fmaxf(fabsf(rx) - hx, 0.0f);
                float my = fmaxf(fabsf(ry) - hy, 0.0f);
                float d2 = fmaf(mx, mx, my * my);
                float inv = rsqrtf(d2);
                float f = fmaxf(fmaf(q.z, inv, -0.5f), 0.0f);
                f = (d2 > EPSF) ? f : 0.0f;
                ax = fmaf(-f, copysignf(mx, rx), ax);
                ay = fmaf(-f, copysignf(my, ry), ay);
            }

            int s2 = max(lo, nc);
            #pragma unroll 4
            for (int t = s2; t < hi; ++t) {
                float4 q = sb[t];
                float dax = px - q.x, day = py - q.y;
                float ovx = (hx + q.z) - fabsf(dax);
                float ovy = (hy + q.w) - fabsf(day);
                bool hit  = (t != self_t) & (ovx > 0.0f) & (ovy > 0.0f);
                bool usex = (ovx <= ovy);
                float pxs = copysignf(0.5f * ovx, dax);
                float pys = copysignf(0.5f * ovy, day);
                ax += (hit & usex)  ? pxs : 0.0f;
                ay += (hit & !usex) ? pys : 0.0f;
            }
        }

        // body-major partial store
        int F = g * 32 + lane;
        g_part[F * C + c] = make_float2(ax, ay);
    }

    // ================= grid barrier (all 444 blocks resident) =================
    __threadfence();
    __syncthreads();
    if (threadIdx.x == 0) {
        unsigned old = g_rel;                    // read before arriving
        unsigned my = atomicAdd(&g_cnt, 1u);
        if (my == gridDim.x - 1) {
            g_cnt = 0;                           // reset for next launch
            __threadfence();
            g_rel = old + 1;                     // release
        } else {
            while (g_rel == old) { }             // spin
        }
        __threadfence();
    }
    __syncthreads();

    // ================= phase 2: one warp per body =================
    {
        int b = blockIdx.x * WPB + warp;         // body index
        int tot = nc + na;
        if (b < tot) {
            int F = (b < nc) ? b : gc * 32 + (b - nc);
            const float2* p = &g_part[F * C];
            float sx = 0.0f, sy = 0.0f;
            for (int cc = lane; cc < C; cc += 32) {
                float2 v = p[cc];
                sx += v.x;
                sy += v.y;
            }
            #pragma unroll
            for (int off = 16; off > 0; off >>= 1) {
                sx += __shfl_xor_sync(0xffffffffu, sx, off);
                sy += __shfl_xor_sync(0xffffffffu, sy, off);
            }
            if (lane == 0) {
                float2 base = (b < nc) ? cpos[b] : apos[b - nc];
                out[b] = make_float2(base.x + sx, base.y + sy);
            }
        }
    }
}

extern "C" void kernel_launch(void* const* d_in, const int* in_sizes, int n_in,
                              void* d_out, int out_size)
{
    const float2* cpos  = (const float2*)d_in[0];
    const float*  crad  = (const float*)d_in[1];
    const float2* apos  = (const float2*)d_in[2];
    const float2* ahalf = (const float2*)d_in[3];
    float2* out = (float2*)d_out;

    int nc = in_sizes[1];        // circle_radius element count
    int na = in_sizes[2] / 2;    // aabb_pos has na*2 elements

    int gc = (nc + 31) / 32;
    int ga = (na + 31) / 32;
    int groups = gc + ga;
    int L = nc + na;

    int C = TARGET_WARPS / groups;            // 192 groups -> 37
    if (C < 1) C = 1;
    // chunk length must fit the shared staging buffer (2*len <= MAX_STAGE)
    int minC = (L + (MAX_STAGE / 2 - 1)) / (MAX_STAGE / 2);
    if (C < minC) C = minC;
    if (groups * C > 16384) C = 16384 / groups;

    int len = (L + C - 1) / C;

    int units = groups * C;
    int grid1 = (units + WPB - 1) / WPB;      // 444 nominal

    fused_kernel<<<grid1, 512>>>(cpos, crad, apos, ahalf, out,
                                 nc, na, gc, groups, C, len);
}

// round 13
// speedup vs baseline: 1.0693x; 1.0626x over previous
#include <cuda_runtime.h>
#include <cuda_bf16.h>

#define EPSF 1e-9f
#define WPB  16              // warps per block (512 threads)
#define TARGET_WARPS 7104    // 148 SMs * 3 blocks * 16 warps
#define MAX_STAGE 352        // max staged bodies per block (2*len)

// partial sums, body-major: g_part[F*C + c], F = g*32 + lane
__device__ float2 g_part[16384 * 32];

__global__ __launch_bounds__(512, 3)
void pairs_kernel(const float2* __restrict__ cpos,
                  const float*  __restrict__ crad,
                  const float2* __restrict__ apos,
                  const float2* __restrict__ ahalf,
                  int nc, int na, int gc, int groups, int C, int len)
{
    __shared__ float4 s_body[MAX_STAGE];

    const int lane = threadIdx.x & 31;
    const int warp = threadIdx.x >> 5;
    const int unit = blockIdx.x * WPB + warp;
    const int L = nc + na;

    // ---- block-level staging: chunk range shared by all warps of this block ----
    const int u0 = blockIdx.x * WPB;
    const int c0 = u0 / groups;
    const int lo_blk = c0 * len;
    const int hi_blk = min(L, lo_blk + 2 * len);

    for (int t = lo_blk + threadIdx.x; t < hi_blk; t += 512) {
        float4 v;
        if (t < nc) {
            float2 p = cpos[t];
            v = make_float4(p.x, p.y, 0.5f * crad[t], 0.0f);
        } else {
            float2 p = apos[t - nc];
            float2 h = ahalf[t - nc];
            v = make_float4(p.x, p.y, h.x, h.y);
        }
        s_body[t - lo_blk] = v;
    }
    __syncthreads();

    if (unit >= groups * C) return;

    const int c = unit / groups;
    const int g = unit - c * groups;
    const int lo = c * len;
    const int hi = min(L, lo + len);
    const float4* __restrict__ sb = s_body - lo_blk;   // index by flattened t

    float ax = 0.0f, ay = 0.0f;

    if (g < gc) {
        // ------------- circle body -------------
        int i  = g * 32 + lane;
        int ii = min(i, nc - 1);
        const float2 pp = cpos[ii];
        const float rih = 0.5f * crad[ii];
        const float px = pp.x, py = pp.y;

        // circle vs circle: t in [lo, min(hi,nc))
        int e1 = min(hi, nc);
        #pragma unroll 8
        for (int t = lo; t < e1; ++t) {
            float4 q = sb[t];
            float dx = px - q.x, dy = py - q.y;
            float d2 = fmaf(dx, dx, dy * dy);
            float rsh = rih + q.z;
            float inv = rsqrtf(d2);                       // inf at d2=0; gated below
            float f = fmaxf(fmaf(rsh, inv, -0.5f), 0.0f);
            f = (d2 > EPSF) ? f : 0.0f;
            ax = fmaf(f, dx, ax);
            ay = fmaf(f, dy, ay);
        }

        // circle vs aabb: t in [max(lo,nc), hi)
        int s2 = max(lo, nc);
        #pragma unroll 4
        for (int t = s2; t < hi; ++t) {
            float4 q = sb[t];
            float rx = px - q.x, ry = py - q.y;
            float mx = fmaxf(fabsf(rx) - q.z, 0.0f);
            float my = fmaxf(fabsf(ry) - q.w, 0.0f);
            float d2 = fmaf(mx, mx, my * my);
            float inv = rsqrtf(d2);
            float f = fmaxf(fmaf(rih, inv, -0.5f), 0.0f);
            f = (d2 > EPSF) ? f : 0.0f;
            ax = fmaf(f, copysignf(mx, rx), ax);
            ay = fmaf(f, copysignf(my, ry), ay);
        }
    } else {
        // ------------- aabb body -------------
        int b  = (g - gc) * 32 + lane;
        int bb = min(b, na - 1);
        const float2 pp = apos[bb];
        const float2 hh = ahalf[bb];
        const float px = pp.x, py = pp.y;
        const float hx = hh.x, hy = hh.y;
        const int self_t = nc + bb;

        // circle pushes on box (equal-and-opposite): t in [lo, min(hi,nc))
        int e1 = min(hi, nc);
        #pragma unroll 4
        for (int t = lo; t < e1; ++t) {
            float4 q = sb[t];
            float rx = q.x - px, ry = q.y - py;
            float mx = fmaxf(fabsf(rx) - hx, 0.0f);
            float my = fmaxf(fabsf(ry) - hy, 0.0f);
            float d2 = fmaf(mx, mx, my * my);
            float inv = rsqrtf(d2);
            float f = fmaxf(fmaf(q.z, inv, -0.5f), 0.0f);
            f = (d2 > EPSF) ? f : 0.0f;
            ax = fmaf(-f, copysignf(mx, rx), ax);
            ay = fmaf(-f, copysignf(my, ry), ay);
        }

        // aabb vs aabb: t in [max(lo,nc), hi)
        int s2 = max(lo, nc);
        #pragma unroll 4
        for (int t = s2; t < hi; ++t) {
            float4 q = sb[t];
            float dax = px - q.x, day = py - q.y;
            float ovx = (hx + q.z) - fabsf(dax);
            float ovy = (hy + q.w) - fabsf(day);
            bool hit  = (t != self_t) & (ovx > 0.0f) & (ovy > 0.0f);
            bool usex = (ovx <= ovy);
            float pxs = copysignf(0.5f * ovx, dax);
            float pys = copysignf(0.5f * ovy, day);
            ax += (hit & usex)  ? pxs : 0.0f;
            ay += (hit & !usex) ? pys : 0.0f;
        }
    }

    // body-major partial store: contiguous C entries per body
    int F = g * 32 + lane;
    g_part[F * C + c] = make_float2(ax, ay);
}

// one warp per body; lanes read the body's C contiguous partials coalesced
__global__ __launch_bounds__(512)
void reduce_warp_kernel(const float2* __restrict__ cpos,
                        const float2* __restrict__ apos,
                        float2* __restrict__ out,
                        int nc, int na, int gc, int C)
{
    const int lane = threadIdx.x & 31;
    const int warp = threadIdx.x >> 5;
    int b = blockIdx.x * WPB + warp;       // body index
    int tot = nc + na;
    if (b >= tot) return;

    int F = (b < nc) ? b : gc * 32 + (b - nc);
    const float2* p = &g_part[F * C];

    float sx = 0.0f, sy = 0.0f;
    for (int cc = lane; cc < C; cc += 32) {
        float2 v = p[cc];
        sx += v.x;
        sy += v.y;
    }
    #pragma unroll
    for (int off = 16; off > 0; off >>= 1) {
        sx += __shfl_xor_sync(0xffffffffu, sx, off);
        sy += __shfl_xor_sync(0xffffffffu, sy, off);
    }
    if (lane == 0) {
        float2 base = (b < nc) ? cpos[b] : apos[b - nc];
        out[b] = make_float2(base.x + sx, base.y + sy);
    }
}

extern "C" void kernel_launch(void* const* d_in, const int* in_sizes, int n_in,
                              void* d_out, int out_size)
{
    const float2* cpos  = (const float2*)d_in[0];
    const float*  crad  = (const float*)d_in[1];
    const float2* apos  = (const float2*)d_in[2];
    const float2* ahalf = (const float2*)d_in[3];
    float2* out = (float2*)d_out;

    int nc = in_sizes[1];        // circle_radius element count
    int na = in_sizes[2] / 2;    // aabb_pos has na*2 elements

    int gc = (nc + 31) / 32;
    int ga = (na + 31) / 32;
    int groups = gc + ga;
    int L = nc + na;

    int C = TARGET_WARPS / groups;            // 192 groups -> 37
    if (C < 1) C = 1;
    // chunk length must fit the shared staging buffer (2*len <= MAX_STAGE)
    int minC = (L + (MAX_STAGE / 2 - 1)) / (MAX_STAGE / 2);
    if (C < minC) C = minC;
    if (groups * C > 16384) C = 16384 / groups;

    int len = (L + C - 1) / C;

    int units = groups * C;
    int grid1 = (units + WPB - 1) / WPB;      // 444 nominal

    pairs_kernel<<<grid1, 512>>>(cpos, crad, apos, ahalf,
                                 nc, na, gc, groups, C, len);

    int tot = nc + na;
    int grid2 = (tot + WPB - 1) / WPB;        // one warp per body, 16 warps/block
    reduce_warp_kernel<<<grid2, 512>>>(cpos, apos, out, nc, na, gc, C);
}